// round 12
// baseline (speedup 1.0000x reference)
#include <cuda_runtime.h>

#define BB 32
#define LL 8192
#define DD 256
#define MM (LL/2 + 1)             // 4097
#define CH 64                     // rows per chunk
#define CHUNKS (LL / CH)          // 128
#define NBLK (BB * CHUNKS)        // 4096
#define OUT_ELEMS ((long long)BB * MM * DD)
#define SX_ROWS (CH + 2)          // prev-halo + 64 rows + next-halo
#define SMEM_BYTES (SX_ROWS * DD * 4)   // 67,584 B dynamic smem
#define NT 512                    // threads per fused block

// Scratch (zero-initialized at module load, re-zeroed by finish_kernel)
__device__ unsigned long long g_state[NBLK];   // lookback: flag<<32 | count
__device__ int g_counts[BB];

// ---------------------------------------------------------------------------
// Single pass per 64-row chunk:
//   A) cooperative copy of rows r0-1 .. r0+64 into SMEM (pure loads, MLP~8)
//   B) 66 sigmoid dots from SMEM (16 warps)
//   C) strict-local-minima mask + local compaction
//   D) warp-parallel windowed lookback for the global output offset
//   E) emit pooled rows from SMEM
// x is read exactly once (+3% halo); no DRAM s array.
// ---------------------------------------------------------------------------
__global__ void __launch_bounds__(NT) fused_kernel(
    const float* __restrict__ x, const float* __restrict__ W,
    const float* __restrict__ bias, float* __restrict__ out, int write_counts)
{
    extern __shared__ __align__(16) float sx[];     // [SX_ROWS][DD]; row j = global row r0+j-1
    __shared__ __align__(16) float sW[DD];
    __shared__ float ss[CH + 2];                    // s for rows r0-1 .. r0+CH
    __shared__ int s_list[CH/2 + 4];
    __shared__ int s_cnt[2];
    __shared__ int s_tot, s_ex;

    int tid = threadIdx.x, lane = tid & 31, warp = tid >> 5;   // 16 warps
    int bid = blockIdx.x;
    int b = bid >> 7;                 // bid / CHUNKS
    int c = bid & (CHUNKS - 1);
    int r0 = c * CH;

    if (tid < DD) sW[tid] = W[tid];

    // --- A: cooperative tile load (66 rows x 64 float4), fully independent ---
    const float* xb = x + (long long)b * LL * DD;
    float4* sx4 = (float4*)sx;
    const float4* xb4 = (const float4*)(xb + (long long)(r0 - 1) * DD);
    const int n4 = SX_ROWS * 64;                  // 4224
    // valid smem-vec4 index range corresponding to global rows in [0, LL)
    int lo4 = (c == 0) ? 64 : 0;                  // skip prev-halo row on first chunk
    int hi4 = (c == CHUNKS - 1) ? (SX_ROWS - 1) * 64 : n4;  // skip next-halo on last
    float4 zq; zq.x = 0.f; zq.y = 0.f; zq.z = 0.f; zq.w = 0.f;
    for (int i = tid; i < n4; i += NT) {
        sx4[i] = (i >= lo4 && i < hi4) ? __ldcs(xb4 + i) : zq;
    }
    __syncthreads();

    // --- B: 66 dots from SMEM ---
    const float4* wv = (const float4*)sW;
    float4 w0 = wv[lane], w1 = wv[lane + 32];
    float bv = bias[0];
    for (int j = warp; j < CH + 2; j += 16) {
        float4 v0 = sx4[j * 64 + lane];
        float4 v1 = sx4[j * 64 + 32 + lane];
        float acc = v0.x*w0.x + v0.y*w0.y + v0.z*w0.z + v0.w*w0.w
                  + v1.x*w1.x + v1.y*w1.y + v1.z*w1.z + v1.w*w1.w;
#pragma unroll
        for (int o = 16; o; o >>= 1) acc += __shfl_xor_sync(0xffffffffu, acc, o);
        if (lane == 0) ss[j] = 1.f / (1.f + expf(-(acc + bv)));
    }
    __syncthreads();

    // --- C: strict-local-minima mask over the 64 owned positions ---
    // (ss[0] for c==0 and ss[CH+1] for the last chunk come from zero-filled
    //  halo rows, but those values are never consumed: l==0 forced true,
    //  l==LL-1 forced false.)
    bool m = false; int pfx = 0;
    if (tid < CH) {
        int l = r0 + tid;
        float cc = ss[tid + 1];
        m = (l == 0) ? true
          : ((l >= LL - 1) ? false : (cc < ss[tid] && cc < ss[tid + 2]));
        unsigned bits = __ballot_sync(0xffffffffu, m);
        pfx = __popc(bits & ((1u << lane) - 1));
        if (lane == 0) s_cnt[warp] = __popc(bits);
    }
    __syncthreads();
    if (tid == 0) s_tot = s_cnt[0] + s_cnt[1];
    if (tid < CH && m) {
        int off = (warp == 1) ? s_cnt[0] : 0;
        s_list[off + pfx] = tid;
    }
    __syncthreads();

    // --- D: warp-parallel windowed lookback (warp 0) ---
    if (warp == 0) {
        int tot = s_tot;
        long long ex = 0;
        if (c != 0) {
            if (lane == 0)
                atomicExch(&g_state[bid], (1ull << 32) | (unsigned)tot);  // AGG
            __syncwarp();
            int begin = b * CHUNKS;
            int base = bid - 1;
            for (;;) {
                int i = base - lane;
                unsigned long long v;
                if (i >= begin) {
                    volatile unsigned long long* p =
                        (volatile unsigned long long*)&g_state[i];
                    v = *p;
                    while ((unsigned)(v >> 32) == 0u) { __nanosleep(32); v = *p; }
                } else {
                    v = (2ull << 32);                 // virtual prefix 0
                }
                unsigned pm = __ballot_sync(0xffffffffu, (unsigned)(v >> 32) == 2u);
                long long contrib;
                if (pm) {
                    int cut = __ffs(pm) - 1;          // nearest PREFIX
                    contrib = (lane <= cut) ? (long long)(unsigned)v : 0;
                } else {
                    contrib = (long long)(unsigned)v; // all AGG: take them all
                }
#pragma unroll
                for (int o = 16; o; o >>= 1)
                    contrib += __shfl_xor_sync(0xffffffffu, contrib, o);
                ex += contrib;
                if (pm) break;
                base -= 32;
            }
        }
        if (lane == 0) {
            atomicExch(&g_state[bid], (2ull << 32) | (unsigned)(ex + tot)); // PREFIX
            s_ex = (int)ex;
            if (c == CHUNKS - 1) {
                int tb = (int)ex + tot;
                g_counts[b] = tb;
                if (write_counts) out[OUT_ELEMS + b] = (float)tb;
            }
        }
    }
    __syncthreads();

    // --- E: emit pooled rows from SMEM: 8 rows in parallel, 64 threads/row ---
    int ex = s_ex, tot = s_tot;
    int grp = tid >> 6, col = tid & 63;
    for (int j0 = grp; j0 < tot; j0 += 8) {
        int t = s_list[j0];                     // local row t -> smem row t+1
        float s0 = ss[t + 1], s1 = ss[t + 2];
        float rden = 1.f / fmaxf(s0 + s1, 1e-6f);
        float a0 = s0 * rden, a1 = s1 * rden;
        float4 v0 = sx4[(t + 1) * 64 + col];
        float4 v1 = sx4[(t + 2) * 64 + col];
        float4 o;
        o.x = a0 * v0.x + a1 * v1.x;
        o.y = a0 * v0.y + a1 * v1.y;
        o.z = a0 * v0.z + a1 * v1.z;
        o.w = a0 * v0.w + a1 * v1.w;
        __stcs((float4*)out + ((long long)b * MM + ex + j0) * 64 + col, o);
    }
}

// ---------------------------------------------------------------------------
// Finish: zero tail rows [count_b, MM) of each batch; reset g_state.
// 2-D grid: y = batch (no division), x = 4-row groups.
// ---------------------------------------------------------------------------
__global__ void __launch_bounds__(256) finish_kernel(float* __restrict__ out) {
    int b = blockIdx.y;
    long long gbid = (long long)b * gridDim.x + blockIdx.x;
    long long gtid = gbid * 256 + threadIdx.x;
    if (gtid < NBLK) g_state[gtid] = 0ull;        // reset for next call

    int k = blockIdx.x * 4 + (threadIdx.x >> 6);
    int cnt = g_counts[b];
    if (k < MM && k >= cnt) {
        float4 z; z.x = 0.f; z.y = 0.f; z.z = 0.f; z.w = 0.f;
        __stcs((float4*)out + ((long long)b * MM + k) * 64 + (threadIdx.x & 63), z);
    }
}

// ---------------------------------------------------------------------------
extern "C" void kernel_launch(void* const* d_in, const int* in_sizes, int n_in,
                              void* d_out, int out_size) {
    const float* x    = (const float*)d_in[0];   // [B, L, D] f32
    // d_in[1]: olens (unused by the reference computation)
    const float* W    = (const float*)d_in[2];   // [D, 1] f32
    const float* bias = (const float*)d_in[3];   // [1] f32

    float* out = (float*)d_out;
    int write_counts = (out_size >= (int)(OUT_ELEMS + BB)) ? 1 : 0;

    cudaFuncSetAttribute(fused_kernel,
                         cudaFuncAttributeMaxDynamicSharedMemorySize, SMEM_BYTES);

    fused_kernel<<<NBLK, NT, SMEM_BYTES>>>(x, W, bias, out, write_counts);
    {
        dim3 grid((MM + 3) / 4, BB);              // 1025 x 32
        finish_kernel<<<grid, 256>>>(out);
    }
}

// round 13
// speedup vs baseline: 1.3403x; 1.3403x over previous
#include <cuda_runtime.h>

#define BB 32
#define LL 8192
#define DD 256
#define MM (LL/2 + 1)             // 4097
#define CH 64                     // rows per chunk
#define CHUNKS (LL / CH)          // 128
#define NBLK (BB * CHUNKS)        // 4096
#define OUT_ELEMS ((long long)BB * MM * DD)
#define SX_ROWS (CH + 2)          // prev-halo + 64 rows + next-halo
#define SMEM_BYTES (SX_ROWS * DD * 4)   // 67,584 B dynamic smem
#define NT 512                    // threads per fused block

// Scratch (zero-initialized at module load, re-zeroed by finish_kernel)
__device__ unsigned long long g_state[NBLK];   // lookback: flag<<32 | count
__device__ int g_counts[BB];

// ---------------------------------------------------------------------------
__device__ __forceinline__ void cpasync16(void* smem_dst, const void* gmem_src) {
    unsigned saddr = (unsigned)__cvta_generic_to_shared(smem_dst);
    asm volatile("cp.async.cg.shared.global [%0], [%1], 16;\n"
                 :: "r"(saddr), "l"(gmem_src));
}

// ---------------------------------------------------------------------------
// Single pass per 64-row chunk:
//   A) cp.async copy of rows r0-1 .. r0+64 into SMEM (no reg deps -> max MLP)
//   B) 66 sigmoid dots from SMEM (16 warps)
//   C) strict-local-minima mask + local compaction
//   D) warp-parallel windowed lookback for the global output offset
//   E) emit pooled rows from SMEM
// x is read exactly once (+3% halo); no DRAM s array.
// ---------------------------------------------------------------------------
__global__ void __launch_bounds__(NT) fused_kernel(
    const float* __restrict__ x, const float* __restrict__ W,
    const float* __restrict__ bias, float* __restrict__ out, int write_counts)
{
    extern __shared__ __align__(16) float sx[];     // [SX_ROWS][DD]; row j = global row r0+j-1
    __shared__ __align__(16) float sW[DD];
    __shared__ float ss[CH + 2];                    // s for rows r0-1 .. r0+CH
    __shared__ int s_list[CH/2 + 4];
    __shared__ int s_cnt[2];
    __shared__ int s_tot, s_ex;

    int tid = threadIdx.x, lane = tid & 31, warp = tid >> 5;   // 16 warps
    int bid = blockIdx.x;
    int b = bid >> 7;                 // bid / CHUNKS
    int c = bid & (CHUNKS - 1);
    int r0 = c * CH;

    if (tid < DD) sW[tid] = W[tid];

    // --- A: async tile copy (66 rows x 64 float4) -----------------------------
    const float* xb = x + (long long)b * LL * DD;
    float4* sx4 = (float4*)sx;
    const float4* xb4 = (const float4*)(xb + (long long)(r0 - 1) * DD);
    const int n4 = SX_ROWS * 64;                  // 4224
    if (c != 0 && c != CHUNKS - 1) {
        // interior chunk: every row valid, unconditional back-to-back cp.async
        for (int i = tid; i < n4; i += NT)
            cpasync16(sx4 + i, xb4 + i);
    } else {
        int lo4 = (c == 0) ? 64 : 0;                        // prev-halo invalid
        int hi4 = (c == CHUNKS - 1) ? (SX_ROWS - 1) * 64 : n4;  // next-halo invalid
        float4 zq; zq.x = 0.f; zq.y = 0.f; zq.z = 0.f; zq.w = 0.f;
        for (int i = tid; i < n4; i += NT) {
            if (i >= lo4 && i < hi4) cpasync16(sx4 + i, xb4 + i);
            else sx4[i] = zq;
        }
    }
    asm volatile("cp.async.commit_group;\n" ::: "memory");
    asm volatile("cp.async.wait_group 0;\n" ::: "memory");
    __syncthreads();

    // --- B: 66 dots from SMEM ---
    const float4* wv = (const float4*)sW;
    float4 w0 = wv[lane], w1 = wv[lane + 32];
    float bv = bias[0];
    for (int j = warp; j < CH + 2; j += 16) {
        float4 v0 = sx4[j * 64 + lane];
        float4 v1 = sx4[j * 64 + 32 + lane];
        float acc = v0.x*w0.x + v0.y*w0.y + v0.z*w0.z + v0.w*w0.w
                  + v1.x*w1.x + v1.y*w1.y + v1.z*w1.z + v1.w*w1.w;
#pragma unroll
        for (int o = 16; o; o >>= 1) acc += __shfl_xor_sync(0xffffffffu, acc, o);
        if (lane == 0) ss[j] = 1.f / (1.f + expf(-(acc + bv)));
    }
    __syncthreads();

    // --- C: strict-local-minima mask over the 64 owned positions ---
    // (halo-derived ss values at the batch edges are never consumed:
    //  l==0 forced true, l==LL-1 forced false.)
    bool m = false; int pfx = 0;
    if (tid < CH) {
        int l = r0 + tid;
        float cc = ss[tid + 1];
        m = (l == 0) ? true
          : ((l >= LL - 1) ? false : (cc < ss[tid] && cc < ss[tid + 2]));
        unsigned bits = __ballot_sync(0xffffffffu, m);
        pfx = __popc(bits & ((1u << lane) - 1));
        if (lane == 0) s_cnt[warp] = __popc(bits);
    }
    __syncthreads();
    if (tid == 0) s_tot = s_cnt[0] + s_cnt[1];
    if (tid < CH && m) {
        int off = (warp == 1) ? s_cnt[0] : 0;
        s_list[off + pfx] = tid;
    }
    __syncthreads();

    // --- D: warp-parallel windowed lookback (warp 0) ---
    if (warp == 0) {
        int tot = s_tot;
        long long ex = 0;
        if (c != 0) {
            if (lane == 0)
                atomicExch(&g_state[bid], (1ull << 32) | (unsigned)tot);  // AGG
            __syncwarp();
            int begin = b * CHUNKS;
            int base = bid - 1;
            for (;;) {
                int i = base - lane;
                unsigned long long v;
                if (i >= begin) {
                    volatile unsigned long long* p =
                        (volatile unsigned long long*)&g_state[i];
                    v = *p;
                    while ((unsigned)(v >> 32) == 0u) { __nanosleep(32); v = *p; }
                } else {
                    v = (2ull << 32);                 // virtual prefix 0
                }
                unsigned pm = __ballot_sync(0xffffffffu, (unsigned)(v >> 32) == 2u);
                long long contrib;
                if (pm) {
                    int cut = __ffs(pm) - 1;          // nearest PREFIX
                    contrib = (lane <= cut) ? (long long)(unsigned)v : 0;
                } else {
                    contrib = (long long)(unsigned)v; // all AGG: take them all
                }
#pragma unroll
                for (int o = 16; o; o >>= 1)
                    contrib += __shfl_xor_sync(0xffffffffu, contrib, o);
                ex += contrib;
                if (pm) break;
                base -= 32;
            }
        }
        if (lane == 0) {
            atomicExch(&g_state[bid], (2ull << 32) | (unsigned)(ex + tot)); // PREFIX
            s_ex = (int)ex;
            if (c == CHUNKS - 1) {
                int tb = (int)ex + tot;
                g_counts[b] = tb;
                if (write_counts) out[OUT_ELEMS + b] = (float)tb;
            }
        }
    }
    __syncthreads();

    // --- E: emit pooled rows from SMEM: 8 rows in parallel, 64 threads/row ---
    int ex = s_ex, tot = s_tot;
    int grp = tid >> 6, col = tid & 63;
    for (int j0 = grp; j0 < tot; j0 += 8) {
        int t = s_list[j0];                     // local row t -> smem row t+1
        float s0 = ss[t + 1], s1 = ss[t + 2];
        float rden = 1.f / fmaxf(s0 + s1, 1e-6f);
        float a0 = s0 * rden, a1 = s1 * rden;
        float4 v0 = sx4[(t + 1) * 64 + col];
        float4 v1 = sx4[(t + 2) * 64 + col];
        float4 o;
        o.x = a0 * v0.x + a1 * v1.x;
        o.y = a0 * v0.y + a1 * v1.y;
        o.z = a0 * v0.z + a1 * v1.z;
        o.w = a0 * v0.w + a1 * v1.w;
        __stcs((float4*)out + ((long long)b * MM + ex + j0) * 64 + col, o);
    }
}

// ---------------------------------------------------------------------------
// Finish: zero tail rows [count_b, MM) of each batch; reset g_state.
// Grid (ceil(MM/16), BB): 16 rows per block, 4 float4 per thread; blocks
// entirely inside the valid region exit after one broadcast load.
// ---------------------------------------------------------------------------
__global__ void __launch_bounds__(256) finish_kernel(float* __restrict__ out) {
    int b = blockIdx.y;
    long long gbid = (long long)b * gridDim.x + blockIdx.x;
    long long gtid = gbid * 256 + threadIdx.x;
    if (gtid < NBLK) g_state[gtid] = 0ull;        // reset for next call

    int cnt = g_counts[b];
    int k0 = blockIdx.x * 16;
    if (k0 + 15 < cnt) return;                    // fully valid block: done

    int col = threadIdx.x & 63;
    int ksub = threadIdx.x >> 6;                  // 0..3
    float4 z; z.x = 0.f; z.y = 0.f; z.z = 0.f; z.w = 0.f;
    float4* ob = (float4*)out + (long long)b * MM * 64;
#pragma unroll
    for (int r = 0; r < 4; r++) {
        int k = k0 + ksub + r * 4;
        if (k < MM && k >= cnt)
            __stcs(ob + (long long)k * 64 + col, z);
    }
}

// ---------------------------------------------------------------------------
extern "C" void kernel_launch(void* const* d_in, const int* in_sizes, int n_in,
                              void* d_out, int out_size) {
    const float* x    = (const float*)d_in[0];   // [B, L, D] f32
    // d_in[1]: olens (unused by the reference computation)
    const float* W    = (const float*)d_in[2];   // [D, 1] f32
    const float* bias = (const float*)d_in[3];   // [1] f32

    float* out = (float*)d_out;
    int write_counts = (out_size >= (int)(OUT_ELEMS + BB)) ? 1 : 0;

    cudaFuncSetAttribute(fused_kernel,
                         cudaFuncAttributeMaxDynamicSharedMemorySize, SMEM_BYTES);

    fused_kernel<<<NBLK, NT, SMEM_BYTES>>>(x, W, bias, out, write_counts);
    {
        dim3 grid((MM + 15) / 16, BB);            // 257 x 32 = 8224 blocks
        finish_kernel<<<grid, 256>>>(out);
    }
}

// round 14
// speedup vs baseline: 1.5662x; 1.1685x over previous
#include <cuda_runtime.h>

#define BB 32
#define LL 8192
#define DD 256
#define MM (LL/2 + 1)             // 4097
#define CH 32                     // rows per chunk
#define CHUNKS (LL / CH)          // 256
#define NBLK (BB * CHUNKS)        // 8192
#define OUT_ELEMS ((long long)BB * MM * DD)
#define SX_ROWS (CH + 2)          // prev-halo + 32 rows + next-halo
#define SMEM_BYTES (SX_ROWS * DD * 4)   // 34,816 B dynamic smem -> 6 CTAs/SM
#define NT 256                    // threads per fused block (8 warps)

// Scratch (zero-initialized at module load, re-zeroed by finish_kernel)
__device__ unsigned long long g_state[NBLK];   // lookback: flag<<32 | count
__device__ int g_counts[BB];

// ---------------------------------------------------------------------------
__device__ __forceinline__ void cpasync16(void* smem_dst, const void* gmem_src) {
    unsigned saddr = (unsigned)__cvta_generic_to_shared(smem_dst);
    asm volatile("cp.async.cg.shared.global [%0], [%1], 16;\n"
                 :: "r"(saddr), "l"(gmem_src));
}

// ---------------------------------------------------------------------------
// Single pass per 32-row chunk:
//   A) cp.async copy of rows r0-1 .. r0+32 into SMEM (no reg deps -> max MLP)
//   B) 34 sigmoid dots from SMEM (8 warps)
//   C) strict-local-minima mask + local compaction (warp 0)
//   D) warp-parallel windowed lookback for the global output offset
//   E) emit pooled rows from SMEM
// x is read exactly once (+6% halo); no DRAM s array.
// ---------------------------------------------------------------------------
__global__ void __launch_bounds__(NT) fused_kernel(
    const float* __restrict__ x, const float* __restrict__ W,
    const float* __restrict__ bias, float* __restrict__ out, int write_counts)
{
    extern __shared__ __align__(16) float sx[];     // [SX_ROWS][DD]; row j = global row r0+j-1
    __shared__ __align__(16) float sW[DD];
    __shared__ float ss[CH + 2];                    // s for rows r0-1 .. r0+CH
    __shared__ int s_list[CH/2 + 4];
    __shared__ int s_tot, s_ex;

    int tid = threadIdx.x, lane = tid & 31, warp = tid >> 5;   // 8 warps
    int bid = blockIdx.x;
    int b = bid >> 8;                 // bid / CHUNKS
    int c = bid & (CHUNKS - 1);
    int r0 = c * CH;

    sW[tid] = W[tid];                 // NT == DD

    // --- A: async tile copy (34 rows x 64 float4) -----------------------------
    const float* xb = x + (long long)b * LL * DD;
    float4* sx4 = (float4*)sx;
    const float4* xb4 = (const float4*)(xb + (long long)(r0 - 1) * DD);
    const int n4 = SX_ROWS * 64;                  // 2176
    if (c != 0 && c != CHUNKS - 1) {
        for (int i = tid; i < n4; i += NT)
            cpasync16(sx4 + i, xb4 + i);
    } else {
        int lo4 = (c == 0) ? 64 : 0;                            // prev-halo invalid
        int hi4 = (c == CHUNKS - 1) ? (SX_ROWS - 1) * 64 : n4;  // next-halo invalid
        float4 zq; zq.x = 0.f; zq.y = 0.f; zq.z = 0.f; zq.w = 0.f;
        for (int i = tid; i < n4; i += NT) {
            if (i >= lo4 && i < hi4) cpasync16(sx4 + i, xb4 + i);
            else sx4[i] = zq;
        }
    }
    asm volatile("cp.async.commit_group;\n" ::: "memory");
    asm volatile("cp.async.wait_group 0;\n" ::: "memory");
    __syncthreads();

    // --- B: 34 dots from SMEM ---
    const float4* wv = (const float4*)sW;
    float4 w0 = wv[lane], w1 = wv[lane + 32];
    float bv = bias[0];
    for (int j = warp; j < CH + 2; j += 8) {
        float4 v0 = sx4[j * 64 + lane];
        float4 v1 = sx4[j * 64 + 32 + lane];
        float acc = v0.x*w0.x + v0.y*w0.y + v0.z*w0.z + v0.w*w0.w
                  + v1.x*w1.x + v1.y*w1.y + v1.z*w1.z + v1.w*w1.w;
#pragma unroll
        for (int o = 16; o; o >>= 1) acc += __shfl_xor_sync(0xffffffffu, acc, o);
        if (lane == 0) ss[j] = 1.f / (1.f + expf(-(acc + bv)));
    }
    __syncthreads();

    // --- C: strict-local-minima mask over the 32 owned positions (warp 0) ---
    // (halo-derived ss values at batch edges are never consumed:
    //  l==0 forced true, l==LL-1 forced false.)
    if (warp == 0) {
        int l = r0 + lane;
        float cc = ss[lane + 1];
        bool m = (l == 0) ? true
               : ((l >= LL - 1) ? false : (cc < ss[lane] && cc < ss[lane + 2]));
        unsigned bits = __ballot_sync(0xffffffffu, m);
        int pfx = __popc(bits & ((1u << lane) - 1));
        if (m) s_list[pfx] = lane;
        int tot = __popc(bits);
        if (lane == 0) s_tot = tot;

        // --- D: warp-parallel windowed lookback (still warp 0) ---
        long long ex = 0;
        if (c != 0) {
            if (lane == 0)
                atomicExch(&g_state[bid], (1ull << 32) | (unsigned)tot);  // AGG
            __syncwarp();
            int begin = b * CHUNKS;
            int base = bid - 1;
            for (;;) {
                int i = base - lane;
                unsigned long long v;
                if (i >= begin) {
                    volatile unsigned long long* p =
                        (volatile unsigned long long*)&g_state[i];
                    v = *p;
                    while ((unsigned)(v >> 32) == 0u) { __nanosleep(32); v = *p; }
                } else {
                    v = (2ull << 32);                 // virtual prefix 0
                }
                unsigned pm = __ballot_sync(0xffffffffu, (unsigned)(v >> 32) == 2u);
                long long contrib;
                if (pm) {
                    int cut = __ffs(pm) - 1;          // nearest PREFIX
                    contrib = (lane <= cut) ? (long long)(unsigned)v : 0;
                } else {
                    contrib = (long long)(unsigned)v; // all AGG: take them all
                }
#pragma unroll
                for (int o = 16; o; o >>= 1)
                    contrib += __shfl_xor_sync(0xffffffffu, contrib, o);
                ex += contrib;
                if (pm) break;
                base -= 32;
            }
        }
        if (lane == 0) {
            atomicExch(&g_state[bid], (2ull << 32) | (unsigned)(ex + tot)); // PREFIX
            s_ex = (int)ex;
            if (c == CHUNKS - 1) {
                int tb = (int)ex + tot;
                g_counts[b] = tb;
                if (write_counts) out[OUT_ELEMS + b] = (float)tb;
            }
        }
    }
    __syncthreads();

    // --- E: emit pooled rows from SMEM: 4 rows in parallel, 64 threads/row ---
    int ex = s_ex, tot = s_tot;
    int grp = tid >> 6, col = tid & 63;
    for (int j0 = grp; j0 < tot; j0 += 4) {
        int t = s_list[j0];                     // local row t -> smem row t+1
        float s0 = ss[t + 1], s1 = ss[t + 2];
        float rden = 1.f / fmaxf(s0 + s1, 1e-6f);
        float a0 = s0 * rden, a1 = s1 * rden;
        float4 v0 = sx4[(t + 1) * 64 + col];
        float4 v1 = sx4[(t + 2) * 64 + col];
        float4 o;
        o.x = a0 * v0.x + a1 * v1.x;
        o.y = a0 * v0.y + a1 * v1.y;
        o.z = a0 * v0.z + a1 * v1.z;
        o.w = a0 * v0.w + a1 * v1.w;
        __stcs((float4*)out + ((long long)b * MM + ex + j0) * 64 + col, o);
    }
}

// ---------------------------------------------------------------------------
// Finish: zero tail rows [count_b, MM) of each batch; reset g_state.
// Grid (ceil(MM/16), BB): 16 rows per block; fully-valid blocks exit early.
// ---------------------------------------------------------------------------
__global__ void __launch_bounds__(256) finish_kernel(float* __restrict__ out) {
    int b = blockIdx.y;
    long long gbid = (long long)b * gridDim.x + blockIdx.x;
    long long gtid = gbid * 256 + threadIdx.x;
    if (gtid < NBLK) g_state[gtid] = 0ull;        // reset for next call

    int cnt = g_counts[b];
    int k0 = blockIdx.x * 16;
    if (k0 + 15 < cnt) return;                    // fully valid block: done

    int col = threadIdx.x & 63;
    int ksub = threadIdx.x >> 6;                  // 0..3
    float4 z; z.x = 0.f; z.y = 0.f; z.z = 0.f; z.w = 0.f;
    float4* ob = (float4*)out + (long long)b * MM * 64;
#pragma unroll
    for (int r = 0; r < 4; r++) {
        int k = k0 + ksub + r * 4;
        if (k < MM && k >= cnt)
            __stcs(ob + (long long)k * 64 + col, z);
    }
}

// ---------------------------------------------------------------------------
extern "C" void kernel_launch(void* const* d_in, const int* in_sizes, int n_in,
                              void* d_out, int out_size) {
    const float* x    = (const float*)d_in[0];   // [B, L, D] f32
    // d_in[1]: olens (unused by the reference computation)
    const float* W    = (const float*)d_in[2];   // [D, 1] f32
    const float* bias = (const float*)d_in[3];   // [1] f32

    float* out = (float*)d_out;
    int write_counts = (out_size >= (int)(OUT_ELEMS + BB)) ? 1 : 0;

    cudaFuncSetAttribute(fused_kernel,
                         cudaFuncAttributeMaxDynamicSharedMemorySize, SMEM_BYTES);

    fused_kernel<<<NBLK, NT, SMEM_BYTES>>>(x, W, bias, out, write_counts);
    {
        dim3 grid((MM + 15) / 16, BB);            // 257 x 32 = 8224 blocks
        finish_kernel<<<grid, 256>>>(out);
    }
}